// round 17
// baseline (speedup 1.0000x reference)
#include <cuda_runtime.h>
#include <math.h>
#include <stdint.h>

// Problem constants
#define B_    2
#define S_    2048
#define H_    4096
#define NH_   32
#define NKV_  2
#define HD_   128
#define ROT_  64
#define QKV_  ((NH_ + 2*NKV_) * HD_)   // 4608
#define MTOK  (B_ * S_)                // 4096

// Scratch (static device globals: no allocation allowed)
__device__ float g_qkv[(size_t)MTOK * QKV_];        // [4096,4608] fp32
__device__ float g_ctx[(size_t)MTOK * NH_ * HD_];   // [4096,4096] tf32-rounded
__device__ float g_hsr[(size_t)MTOK * H_];          // hs rounded to tf32
__device__ float g_wqr[(size_t)H_ * QKV_];          // Wqkv rounded
__device__ float g_wor[(size_t)H_ * H_];            // Wo rounded
// attention pre-packed operands
__device__ float g_qp[(size_t)MTOK * NH_ * HD_];    // Q scaled+rounded, hd-paired
__device__ float g_kp[(size_t)MTOK * NKV_ * HD_];   // K rounded, hd-paired
__device__ float g_vt[(size_t)B_ * NKV_ * HD_ * S_];// V rounded, [b][kv][hd][seq-paired]
__device__ int   g_posflag;

// ===========================================================================
// helpers
// ===========================================================================
#define CP_ASYNC16(dst_smem, src_gmem) \
    asm volatile("cp.async.cg.shared.global [%0], [%1], 16;" \
                 :: "r"(dst_smem), "l"(src_gmem) : "memory")
#define CP_COMMIT() asm volatile("cp.async.commit_group;" ::: "memory")
#define CP_WAIT(n)  asm volatile("cp.async.wait_group %0;" :: "n"(n) : "memory")

__device__ __forceinline__ uint32_t smem_to_u32(const void* p) {
    uint32_t a;
    asm("{ .reg .u64 t; cvta.to.shared.u64 t, %1; cvt.u32.u64 %0, t; }"
        : "=r"(a) : "l"(p));
    return a;
}
__device__ __forceinline__ uint32_t cvt_rna(float x) {
    uint32_t r;
    asm("cvt.rna.tf32.f32 %0, %1;" : "=r"(r) : "f"(x));
    return r;
}
__device__ __forceinline__ float rna_f(float x) {
    return __uint_as_float(cvt_rna(x));
}
__device__ __forceinline__ void mma_tf32(float* c, const uint32_t* a, const uint32_t* b) {
    asm volatile(
        "mma.sync.aligned.m16n8k8.row.col.f32.tf32.tf32.f32 "
        "{%0,%1,%2,%3}, {%4,%5,%6,%7}, {%8,%9}, {%0,%1,%2,%3};"
        : "+f"(c[0]), "+f"(c[1]), "+f"(c[2]), "+f"(c[3])
        : "r"(a[0]), "r"(a[1]), "r"(a[2]), "r"(a[3]), "r"(b[0]), "r"(b[1]));
}
// paired column position within 8-groups: j -> (j&3)*2 + (j>>2)
__device__ __forceinline__ int ppos(int c) {
    return ((c >> 3) << 3) + ((c & 3) * 2) + ((c >> 2) & 1);
}

// ===========================================================================
// pre-round pass: out[i] = tf32_rna(in[i])
// ===========================================================================
__global__ void round_copy_kernel(const float* __restrict__ in,
                                  float* __restrict__ out, int n4) {
    int i = blockIdx.x * blockDim.x + threadIdx.x;
    if (i >= n4) return;
    float4 v = ((const float4*)in)[i];
    v.x = rna_f(v.x); v.y = rna_f(v.y);
    v.z = rna_f(v.z); v.w = rna_f(v.w);
    ((float4*)out)[i] = v;
}

// ===========================================================================
// attention operand prep: after rope, build
//   g_qp [t][h][hd-paired]     = rna(Q * scale)
//   g_kp [t][kv][hd-paired]    = rna(K)
//   g_vt [b][kv][hd][seq-pair] = rna(V)
// ===========================================================================
__global__ void prep_attn_kernel() {
    const float scale = 0.08838834764831845f;
    const int total = MTOK * (NH_ + 2 * NKV_) * HD_;
    int idx = blockIdx.x * blockDim.x + threadIdx.x;
    if (idx >= total) return;
    const int d    = idx & (HD_ - 1);
    const int head = (idx >> 7) % (NH_ + 2 * NKV_);
    const int t    = idx / (HD_ * (NH_ + 2 * NKV_));
    const float x  = g_qkv[(size_t)t * QKV_ + head * HD_ + d];
    if (head < NH_) {
        g_qp[((size_t)t * NH_ + head) * HD_ + ppos(d)] = rna_f(x * scale);
    } else if (head < NH_ + NKV_) {
        const int kv = head - NH_;
        g_kp[((size_t)t * NKV_ + kv) * HD_ + ppos(d)] = rna_f(x);
    } else {
        const int kv = head - NH_ - NKV_;
        const int b  = t >> 11;           // / S_
        const int s  = t & (S_ - 1);
        const int sp = ((s >> 3) << 3) + ((s & 3) * 2) + ((s >> 2) & 1);
        g_vt[(((size_t)(b * NKV_ + kv)) * HD_ + d) * S_ + sp] = rna_f(x);
    }
}

// ===========================================================================
// tf32 mma.sync GEMM: CTA 128x128, BK=32, 3-stage, SINGLE barrier per k-iter
// (wait -> barrier -> issue kc+2 -> compute kc; overwrite of stage (kc-1)%3
// is safe because barrier kc implies all warps finished compute kc-1).
// ===========================================================================
#define APITCH 36
#define BPITCH 136
#define ASTAGE (128 * APITCH * 4)
#define BSTAGE (32 * BPITCH * 4)
#define STAGE_BYTES (ASTAGE + BSTAGE)
#define GEMM_DSMEM (3 * STAGE_BYTES)

__global__ void __launch_bounds__(256, 2) gemm_tf32_kernel(
    const float* __restrict__ A, const float* __restrict__ Bm,
    const float* __restrict__ bias, float* __restrict__ C,
    int M, int N, int K, int mTiles, int nTiles, int group)
{
    extern __shared__ float dsm[];

    const int tid  = threadIdx.x;
    const int wid  = tid >> 5;
    const int lane = tid & 31;
    const int g    = lane >> 2;
    const int tig  = lane & 3;
    const int wm   = wid & 1;
    const int wn   = wid >> 1;

    const int bid = blockIdx.x;
    const int tpg = group * nTiles;
    const int gi  = bid / tpg;
    const int rr  = bid % tpg;
    const int rem = mTiles - gi * group;
    const int gm  = rem < group ? rem : group;
    const int tm  = gi * group + rr % gm;
    const int tn  = rr / gm;
    const int m0  = tm * 128;
    const int n0  = tn * 128;

    const uint32_t base_u = smem_to_u32(dsm);

    auto load_stage = [&](int s, int kc) {
        const uint32_t sA = base_u + s * STAGE_BYTES;
        const uint32_t sB = sA + ASTAGE;
        const float* Ab = A + (size_t)m0 * K + kc * 32;
        const float* Bb = Bm + (size_t)(kc * 32) * N + n0;
#pragma unroll
        for (int i = 0; i < 4; ++i) {
            const int id  = tid + i * 256;
            const int row = id >> 3;
            const int gg  = id & 7;
            CP_ASYNC16(sA + row * (APITCH * 4) + gg * 16,
                       Ab + (size_t)row * K + gg * 4);
        }
#pragma unroll
        for (int i = 0; i < 4; ++i) {
            const int id  = tid + i * 256;
            const int row = id >> 5;
            const int gg  = id & 31;
            CP_ASYNC16(sB + row * (BPITCH * 4) + gg * 16,
                       Bb + (size_t)row * N + gg * 4);
        }
    };

    float acc[4][4][4];
#pragma unroll
    for (int mt = 0; mt < 4; ++mt)
#pragma unroll
        for (int nt = 0; nt < 4; ++nt)
#pragma unroll
            for (int r = 0; r < 4; ++r) acc[mt][nt][r] = 0.f;

    const int NK = K / 32;
    load_stage(0, 0); CP_COMMIT();
    load_stage(1, 1); CP_COMMIT();

    int s_next = 2;
    for (int kc = 0; kc < NK; ++kc) {
        if (kc + 1 < NK) { CP_WAIT(1); } else { CP_WAIT(0); }
        __syncthreads();
        if (kc + 2 < NK) {
            load_stage(s_next, kc + 2); CP_COMMIT();
            if (++s_next == 3) s_next = 0;
        }

        const int s = kc % 3;
        const float* As = dsm + (size_t)s * (STAGE_BYTES / 4);
        const float* Bs = As + ASTAGE / 4;

#pragma unroll
        for (int ks = 0; ks < 4; ++ks) {
            uint32_t af[4][4];
#pragma unroll
            for (int mt = 0; mt < 4; ++mt) {
                const int r0 = wm * 64 + mt * 16 + g;
                const int c0 = ks * 8 + tig;
                af[mt][0] = __float_as_uint(As[(r0    ) * APITCH + c0    ]);
                af[mt][1] = __float_as_uint(As[(r0 + 8) * APITCH + c0    ]);
                af[mt][2] = __float_as_uint(As[(r0    ) * APITCH + c0 + 4]);
                af[mt][3] = __float_as_uint(As[(r0 + 8) * APITCH + c0 + 4]);
            }
            uint32_t bf[4][2];
#pragma unroll
            for (int nt = 0; nt < 4; ++nt) {
                const int cn = wn * 32 + nt * 8 + g;
                bf[nt][0] = __float_as_uint(Bs[(ks * 8 + tig    ) * BPITCH + cn]);
                bf[nt][1] = __float_as_uint(Bs[(ks * 8 + tig + 4) * BPITCH + cn]);
            }
#pragma unroll
            for (int mt = 0; mt < 4; ++mt)
#pragma unroll
                for (int nt = 0; nt < 4; ++nt)
                    mma_tf32(acc[mt][nt], af[mt], bf[nt]);
        }
    }

#pragma unroll
    for (int mt = 0; mt < 4; ++mt) {
        const int row = m0 + wm * 64 + mt * 16 + g;
#pragma unroll
        for (int nt = 0; nt < 4; ++nt) {
            const int col = n0 + wn * 32 + nt * 8 + tig * 2;
            float b0 = 0.f, b1 = 0.f;
            if (bias) { b0 = bias[col]; b1 = bias[col + 1]; }
            float2 v0, v1;
            v0.x = acc[mt][nt][0] + b0; v0.y = acc[mt][nt][1] + b1;
            v1.x = acc[mt][nt][2] + b0; v1.y = acc[mt][nt][3] + b1;
            *(float2*)&C[(size_t)row * N + col]       = v0;
            *(float2*)&C[(size_t)(row + 8) * N + col] = v1;
        }
    }
}

// ===========================================================================
// position dtype detection
// ===========================================================================
__global__ void detect_pos_kernel(const int* __restrict__ p32) {
    if (threadIdx.x == 0 && blockIdx.x == 0)
        g_posflag = (p32[1] == 1 && p32[2] == 2) ? 1 : 0;
}

// ===========================================================================
// RoPE (GPT-J interleaved), in-place on q heads 0..31 and k heads 32..33
// ===========================================================================
__global__ void rope_kernel(const void* __restrict__ posraw) {
    const int total = MTOK * (NH_ + NKV_) * (ROT_ / 2);
    int idx = blockIdx.x * blockDim.x + threadIdx.x;
    if (idx >= total) return;

    const int i    = idx & 31;
    const int head = (idx >> 5) % (NH_ + NKV_);
    const int t    = idx / (32 * (NH_ + NKV_));

    long long pos;
    if (g_posflag) pos = ((const int*)posraw)[t];
    else           pos = ((const long long*)posraw)[t];

    const double e  = (double)(2 * i) / 64.0;
    const float inv = (float)(1.0 / pow(10000.0, e));
    const float fr  = (float)pos * inv;
    float sn, cs;
    sincosf(fr, &sn, &cs);

    size_t col;
    if (head < NH_) col = (size_t)head * HD_ + 2 * i;
    else            col = (size_t)NH_ * HD_ + (size_t)(head - NH_) * HD_ + 2 * i;

    float* p = g_qkv + (size_t)t * QKV_ + col;
    const float x1 = p[0];
    const float x2 = p[1];
    p[0] = x1 * cs - x2 * sn;
    p[1] = x2 * cs + x1 * sn;
}

// ===========================================================================
// Tensor-core flash attention, causal, GQA. BQ=128, 8 m-warps, BK=16.
// Pre-packed operands (paired cols -> LDS.64), cp.async K/V double-buffer,
// 1 barrier per tile, 2 CTAs/SM.
// NEW: LPT scheduling (heaviest q-tiles first) + alpha==1 rescale skip.
// ===========================================================================
#define QPIT 136
#define KPIT 136
#define VPIT 24
#define KSTG (16 * KPIT * 4)            // 8704 B
#define VSTG (128 * VPIT * 4)           // 12288 B
#define ATTN_SMEM (128*QPIT*4 + 2*(KSTG + VSTG))   // 111616 B

__global__ void __launch_bounds__(256, 2) attn_kernel() {
    extern __shared__ float sm[];
    float* Qs  = sm;                    // [128][136] paired cols
    float* Kst = Qs + 128 * QPIT;       // [2][16][136] paired cols
    float* Vst = Kst + 2 * 16 * KPIT;   // [2][128][24] paired seq cols

    const int tid  = threadIdx.x;
    const int wid  = tid >> 5;
    const int lane = tid & 31;
    const int g    = lane >> 2;
    const int tig  = lane & 3;
    const int wrow = wid * 16;

    // LPT: heaviest q-tiles (largest qt) launch first
    const int qt = (int)gridDim.x - 1 - (int)blockIdx.x;
    const int bh = blockIdx.y;
    const int b  = bh >> 5;
    const int h  = bh & 31;
    const int kh = h >> 4;
    const int q0 = qt * 128;

    const uint32_t qs_u = smem_to_u32(Qs);
    const uint32_t ks_u = smem_to_u32(Kst);
    const uint32_t vs_u = smem_to_u32(Vst);

    const float* Qg = g_qp + ((size_t)(b * S_ + q0) * NH_ + h) * HD_;
    const float* Kg = g_kp + (size_t)b * S_ * NKV_ * HD_ + (size_t)kh * HD_;
    const float* Vg = g_vt + (size_t)(b * NKV_ + kh) * HD_ * S_;

    const int NT = 8 * qt + 8;

    auto load_kv = [&](int kt, int s) {
        const float* Kb = Kg + (size_t)(kt * 16) * (NKV_ * HD_);
        const float* Vb = Vg + kt * 16;
        const uint32_t kd = ks_u + s * KSTG;
        const uint32_t vd = vs_u + s * VSTG;
#pragma unroll
        for (int i = 0; i < 2; ++i) {   // K: 16 rows x 32 chunks
            const int id  = tid + i * 256;
            const int row = id >> 5;
            const int ch  = id & 31;
            CP_ASYNC16(kd + row * (KPIT * 4) + ch * 16,
                       Kb + (size_t)row * (NKV_ * HD_) + ch * 4);
        }
#pragma unroll
        for (int i = 0; i < 2; ++i) {   // V: 128 rows x 4 chunks
            const int id  = tid + i * 256;
            const int row = id >> 2;
            const int ch  = id & 3;
            CP_ASYNC16(vd + row * (VPIT * 4) + ch * 16,
                       Vb + (size_t)row * S_ + ch * 4);
        }
    };

    // prologue: Q (whole tile) + K0/V0 as group 0
#pragma unroll
    for (int i = 0; i < 16; ++i) {      // Q: 128 rows x 32 chunks
        const int id  = tid + i * 256;
        const int row = id >> 5;
        const int ch  = id & 31;
        CP_ASYNC16(qs_u + row * (QPIT * 4) + ch * 16,
                   Qg + (size_t)row * (NH_ * HD_) + ch * 4);
    }
    load_kv(0, 0);
    CP_COMMIT();

    float m_iA = -INFINITY, m_iB = -INFINITY, l_iA = 0.f, l_iB = 0.f;
    float O[16][4];
#pragma unroll
    for (int nf = 0; nf < 16; ++nf) {
        O[nf][0] = 0.f; O[nf][1] = 0.f; O[nf][2] = 0.f; O[nf][3] = 0.f;
    }

    for (int kt = 0; kt < NT; ++kt) {
        const int s  = kt & 1;
        const int k0 = kt * 16;

        CP_WAIT(0);
        __syncthreads();

        if (kt + 1 < NT) {
            load_kv(kt + 1, s ^ 1);
            CP_COMMIT();
        }

        const float* Kh = Kst + s * (KSTG / 4);
        const float* Vt = Vst + s * (VSTG / 4);

        // ---- S = Q K^T (1-term tf32, LDS.64 fragments) ----
        float sacc[2][4];
#pragma unroll
        for (int nf = 0; nf < 2; ++nf) {
            sacc[nf][0] = 0.f; sacc[nf][1] = 0.f; sacc[nf][2] = 0.f; sacc[nf][3] = 0.f;
        }
#pragma unroll
        for (int ks = 0; ks < 16; ++ks) {
            const int co = ks * 8 + tig * 2;
            const float2 qa = *(const float2*)&Qs[(wrow + g    ) * QPIT + co];
            const float2 qb = *(const float2*)&Qs[(wrow + g + 8) * QPIT + co];
            uint32_t ah[4];
            ah[0] = __float_as_uint(qa.x); ah[1] = __float_as_uint(qb.x);
            ah[2] = __float_as_uint(qa.y); ah[3] = __float_as_uint(qb.y);
#pragma unroll
            for (int nf = 0; nf < 2; ++nf) {
                const float2 kb = *(const float2*)&Kh[(nf * 8 + g) * KPIT + co];
                uint32_t bk[2];
                bk[0] = __float_as_uint(kb.x); bk[1] = __float_as_uint(kb.y);
                mma_tf32(sacc[nf], ah, bk);
            }
        }

        // ---- causal mask ----
        const int rowA = q0 + wrow + g;
        const int rowB = rowA + 8;
        if (k0 + 15 > rowA) {
#pragma unroll
            for (int nf = 0; nf < 2; ++nf) {
                const int col = k0 + nf * 8 + tig * 2;
                if (col     > rowA) sacc[nf][0] = -INFINITY;
                if (col + 1 > rowA) sacc[nf][1] = -INFINITY;
                if (col     > rowB) sacc[nf][2] = -INFINITY;
                if (col + 1 > rowB) sacc[nf][3] = -INFINITY;
            }
        }

        // ---- online softmax (fp32, warp-local rows) ----
        float mA = fmaxf(fmaxf(sacc[0][0], sacc[0][1]), fmaxf(sacc[1][0], sacc[1][1]));
        float mB = fmaxf(fmaxf(sacc[0][2], sacc[0][3]), fmaxf(sacc[1][2], sacc[1][3]));
        mA = fmaxf(mA, __shfl_xor_sync(0xffffffffu, mA, 1));
        mA = fmaxf(mA, __shfl_xor_sync(0xffffffffu, mA, 2));
        mB = fmaxf(mB, __shfl_xor_sync(0xffffffffu, mB, 1));
        mB = fmaxf(mB, __shfl_xor_sync(0xffffffffu, mB, 2));

        const float mnA = fmaxf(m_iA, mA);
        const float mnB = fmaxf(m_iB, mB);
        const float aA  = __expf(m_iA - mnA);
        const float aB  = __expf(m_iB - mnB);
        m_iA = mnA; m_iB = mnB;

        uint32_t Pr[2][4];
        float rsA = 0.f, rsB = 0.f;
#pragma unroll
        for (int nf = 0; nf < 2; ++nf) {
            const float p0 = __expf(sacc[nf][0] - mnA);
            const float p1 = __expf(sacc[nf][1] - mnA);
            const float p2 = __expf(sacc[nf][2] - mnB);
            const float p3 = __expf(sacc[nf][3] - mnB);
            rsA += p0 + p1; rsB += p2 + p3;
            Pr[nf][0] = cvt_rna(p0); Pr[nf][1] = cvt_rna(p1);
            Pr[nf][2] = cvt_rna(p2); Pr[nf][3] = cvt_rna(p3);
        }
        rsA += __shfl_xor_sync(0xffffffffu, rsA, 1);
        rsA += __shfl_xor_sync(0xffffffffu, rsA, 2);
        rsB += __shfl_xor_sync(0xffffffffu, rsB, 1);
        rsB += __shfl_xor_sync(0xffffffffu, rsB, 2);
        l_iA = l_iA * aA + rsA;
        l_iB = l_iB * aB + rsB;

        // rescale O only if some row's max actually moved (alpha==1 is exact
        // when the max is unchanged: __expf(0)==1 -> skipping is bit-identical)
        if (__any_sync(0xffffffffu, (aA != 1.f) || (aB != 1.f))) {
#pragma unroll
            for (int nf = 0; nf < 16; ++nf) {
                O[nf][0] *= aA; O[nf][1] *= aA;
                O[nf][2] *= aB; O[nf][3] *= aB;
            }
        }

        // ---- O += P V: shfl-permute P acc-frag -> A-frag, LDS.64 B ----
#pragma unroll
        for (int ks = 0; ks < 2; ++ks) {
            const int src1 = (lane & 28) | (tig >> 1);
            const int src2 = src1 + 2;
            const uint32_t u00 = __shfl_sync(0xffffffffu, Pr[ks][0], src1);
            const uint32_t u01 = __shfl_sync(0xffffffffu, Pr[ks][1], src1);
            const uint32_t u10 = __shfl_sync(0xffffffffu, Pr[ks][2], src1);
            const uint32_t u11 = __shfl_sync(0xffffffffu, Pr[ks][3], src1);
            const uint32_t u20 = __shfl_sync(0xffffffffu, Pr[ks][0], src2);
            const uint32_t u21 = __shfl_sync(0xffffffffu, Pr[ks][1], src2);
            const uint32_t u30 = __shfl_sync(0xffffffffu, Pr[ks][2], src2);
            const uint32_t u31 = __shfl_sync(0xffffffffu, Pr[ks][3], src2);
            uint32_t ap[4];
            ap[0] = (tig & 1) ? u01 : u00;
            ap[1] = (tig & 1) ? u11 : u10;
            ap[2] = (tig & 1) ? u21 : u20;
            ap[3] = (tig & 1) ? u31 : u30;
            const int co = ks * 8 + tig * 2;
#pragma unroll
            for (int nf = 0; nf < 16; ++nf) {
                const float2 vv = *(const float2*)&Vt[(nf * 8 + g) * VPIT + co];
                uint32_t bv[2];
                bv[0] = __float_as_uint(vv.x); bv[1] = __float_as_uint(vv.y);
                mma_tf32(O[nf], ap, bv);
            }
        }
    }

    // ---- epilogue: normalize, tf32-round, store ctx [B,S,NH,HD] ----
    const float invA = 1.f / l_iA;
    const float invB = 1.f / l_iB;
    const size_t baseA = ((size_t)(b * S_ + q0 + wrow + g    ) * NH_ + h) * HD_;
    const size_t baseB = ((size_t)(b * S_ + q0 + wrow + g + 8) * NH_ + h) * HD_;
#pragma unroll
    for (int nf = 0; nf < 16; ++nf) {
        const int col = nf * 8 + tig * 2;
        *(float2*)&g_ctx[baseA + col] =
            make_float2(rna_f(O[nf][0] * invA), rna_f(O[nf][1] * invA));
        *(float2*)&g_ctx[baseB + col] =
            make_float2(rna_f(O[nf][2] * invB), rna_f(O[nf][3] * invB));
    }
}

// ===========================================================================
// Launch
// ===========================================================================
extern "C" void kernel_launch(void* const* d_in, const int* in_sizes, int n_in,
                              void* d_out, int out_size)
{
    const float* hs   = (const float*)d_in[0];
    const void*  pos  = d_in[1];
    const float* Wqkv = (const float*)d_in[2];
    const float* bqkv = (const float*)d_in[3];
    const float* Wo   = (const float*)d_in[4];
    float*       out  = (float*)d_out;

    float *qkv, *ctx, *hsr, *wqr, *wor;
    cudaGetSymbolAddress((void**)&qkv, g_qkv);
    cudaGetSymbolAddress((void**)&ctx, g_ctx);
    cudaGetSymbolAddress((void**)&hsr, g_hsr);
    cudaGetSymbolAddress((void**)&wqr, g_wqr);
    cudaGetSymbolAddress((void**)&wor, g_wor);

    cudaFuncSetAttribute(attn_kernel,
                         cudaFuncAttributeMaxDynamicSharedMemorySize, ATTN_SMEM);
    cudaFuncSetAttribute(gemm_tf32_kernel,
                         cudaFuncAttributeMaxDynamicSharedMemorySize, GEMM_DSMEM);

    // 0) pre-round GEMM operands to tf32
    {
        int n4 = MTOK * H_ / 4;
        round_copy_kernel<<<(n4 + 255) / 256, 256>>>(hs, hsr, n4);
        n4 = H_ * QKV_ / 4;
        round_copy_kernel<<<(n4 + 255) / 256, 256>>>(Wqkv, wqr, n4);
        n4 = H_ * H_ / 4;
        round_copy_kernel<<<(n4 + 255) / 256, 256>>>(Wo, wor, n4);
    }

    // 1) QKV projection (tf32 mma.sync)
    gemm_tf32_kernel<<<(MTOK / 128) * (QKV_ / 128), 256, GEMM_DSMEM>>>(
        hsr, wqr, bqkv, qkv, MTOK, QKV_, H_, MTOK / 128, QKV_ / 128, 8);

    // 2) position dtype detect + RoPE in-place
    detect_pos_kernel<<<1, 32>>>((const int*)pos);
    {
        const int total = MTOK * (NH_ + NKV_) * (ROT_ / 2);
        rope_kernel<<<(total + 255) / 256, 256>>>(pos);
    }

    // 2b) pack attention operands (round/scale/pair/transpose)
    {
        const int total = MTOK * (NH_ + 2 * NKV_) * HD_;
        prep_attn_kernel<<<(total + 255) / 256, 256>>>();
    }

    // 3) tensor-core causal GQA flash attention -> g_ctx (tf32-rounded)
    attn_kernel<<<dim3(S_ / 128, B_ * NH_), 256, ATTN_SMEM>>>();

    // 4) output projection (tf32 mma.sync)
    gemm_tf32_kernel<<<(MTOK / 128) * (H_ / 128), 256, GEMM_DSMEM>>>(
        ctx, wor, nullptr, out, MTOK, H_, H_, MTOK / 128, H_ / 128, 8);
}